// round 6
// baseline (speedup 1.0000x reference)
#include <cuda_runtime.h>

// Beamform_1649267442279 — GB300 sm_103a — R6: 4 blocks/thread at
// quarter-channel spacing -> MLP_p1=16 front-batched LDG.64, four compact
// 1KB warp windows (R5 confirmed: DRAM% scales with per-thread MLP when
// warp windows stay compact).
//
// Semantics: per channel s, blocks of 20 complex samples (40 floats).
// Block b, row r (0..3), col c (0..4):
//   re[r,c] = in_s[40b + 10r + 2c],  im[r,c] = in_s[40b + 10r + 2c + 1]
//   out[(s*Bc+b)*10 + c]     = sum_r br[r]*re - bi[r]*im
//   out[(s*Bc+b)*10 + 5 + c] = sum_r bi[r]*re + br[r]*im
// with br[r]=bf[2r], bi[r]=bf[2r+1].

__device__ __forceinline__ void cmac4(float& re, float& im,
                                      const float4 w0, const float4 w1,
                                      const float2 v0, const float2 v1,
                                      const float2 v2, const float2 v3)
{
    re  = w0.x * v0.x - w0.y * v0.y;
    im  = w0.y * v0.x + w0.x * v0.y;
    re += w0.z * v1.x - w0.w * v1.y;
    im += w0.w * v1.x + w0.z * v1.y;
    re += w1.x * v2.x - w1.y * v2.y;
    im += w1.y * v2.x + w1.x * v2.y;
    re += w1.z * v3.x - w1.w * v3.y;
    im += w1.w * v3.x + w1.z * v3.y;
}

__global__ void __launch_bounds__(256)
beamform_kernel(const float* __restrict__ in0,
                const float* __restrict__ in1,
                const float* __restrict__ in2,
                const float* __restrict__ in3,
                const float* __restrict__ bf,
                float* __restrict__ out,
                int quarter_blocks,    // Bc / 4
                int blocks_per_ch)     // Bc
{
    const int g = blockIdx.x * blockDim.x + threadIdx.x;
    if (g >= quarter_blocks * 5) return;

    const int ch = blockIdx.y;
    const float* __restrict__ in =
        (ch == 0) ? in0 : (ch == 1) ? in1 : (ch == 2) ? in2 : in3;

    const int b = g / 5;            // block within first quarter
    const int j = g - b * 5;        // column 0..4

    const size_t qstride = (size_t)quarter_blocks * 20;   // float2 per quarter

    // ---- front-batched loads: 16 independent LDG.64, 4 compact windows ----
    const float2* __restrict__ pA =
        (const float2*)(in + (size_t)b * 40 + 2 * j);
    const float2* __restrict__ pB = pA + qstride;
    const float2* __restrict__ pC = pB + qstride;
    const float2* __restrict__ pD = pC + qstride;

    const float2 a0 = __ldg(pA + 0),  a1 = __ldg(pA + 5);
    const float2 a2 = __ldg(pA + 10), a3 = __ldg(pA + 15);
    const float2 b0 = __ldg(pB + 0),  b1 = __ldg(pB + 5);
    const float2 b2 = __ldg(pB + 10), b3 = __ldg(pB + 15);
    const float2 c0 = __ldg(pC + 0),  c1 = __ldg(pC + 5);
    const float2 c2 = __ldg(pC + 10), c3 = __ldg(pC + 15);
    const float2 d0 = __ldg(pD + 0),  d1 = __ldg(pD + 5);
    const float2 d2 = __ldg(pD + 10), d3 = __ldg(pD + 15);

    // weights: uniform-address broadcast, L1-resident
    const float4 w0 = __ldg((const float4*)bf);      // br0, bi0, br1, bi1
    const float4 w1 = __ldg((const float4*)bf + 1);  // br2, bi2, br3, bi3

    float reA, imA, reB, imB, reC, imC, reD, imD;
    cmac4(reA, imA, w0, w1, a0, a1, a2, a3);
    cmac4(reB, imB, w0, w1, b0, b1, b2, b3);
    cmac4(reC, imC, w0, w1, c0, c1, c2, c3);
    cmac4(reD, imD, w0, w1, d0, d1, d2, d3);

    const size_t oq = (size_t)quarter_blocks * 10;
    const size_t ob = ((size_t)ch * blocks_per_ch + (size_t)b) * 10;
    out[ob + j]              = reA;
    out[ob + 5 + j]          = imA;
    out[ob + oq + j]         = reB;
    out[ob + oq + 5 + j]     = imB;
    out[ob + 2 * oq + j]     = reC;
    out[ob + 2 * oq + 5 + j] = imC;
    out[ob + 3 * oq + j]     = reD;
    out[ob + 3 * oq + 5 + j] = imD;
}

extern "C" void kernel_launch(void* const* d_in, const int* in_sizes, int n_in,
                              void* d_out, int out_size)
{
    const float* in0 = (const float*)d_in[0];
    const float* in1 = (const float*)d_in[1];
    const float* in2 = (const float*)d_in[2];
    const float* in3 = (const float*)d_in[3];
    const float* bf  = (const float*)d_in[4];
    float* out = (float*)d_out;

    const int N  = in_sizes[0];          // 20,000,000 floats / channel
    const int Bc = N / 40;               // 500,000 beam blocks per channel
    const int Qb = Bc / 4;               // 125,000 blocks per quarter

    const int threads = 256;
    const int n_thr = Qb * 5;            // 625,000 threads per channel
    dim3 grid((n_thr + threads - 1) / threads, 4);

    beamform_kernel<<<grid, threads>>>(in0, in1, in2, in3, bf, out, Qb, Bc);
}

// round 7
// speedup vs baseline: 1.0341x; 1.0341x over previous
#include <cuda_runtime.h>

// Beamform_1649267442279 — GB300 sm_103a — R7: R6's 4-blocks/thread MLP=16
// with the register budget unlocked (__launch_bounds__(256, 1)).
// R6 failed because ptxas capped regs at 32 -> could not keep 16 float2 in
// flight -> loads serialized, MLP collapsed. minBlocksPerMultiprocessor=1
// lets ptxas allocate ~56 regs and keep all loads outstanding.
//
// Semantics: per channel s, blocks of 20 complex samples (40 floats).
// Block b, row r (0..3), col c (0..4):
//   re[r,c] = in_s[40b + 10r + 2c],  im[r,c] = in_s[40b + 10r + 2c + 1]
//   out[(s*Bc+b)*10 + c]     = sum_r br[r]*re - bi[r]*im
//   out[(s*Bc+b)*10 + 5 + c] = sum_r bi[r]*re + br[r]*im
// with br[r]=bf[2r], bi[r]=bf[2r+1].

__device__ __forceinline__ void cmac4(float& re, float& im,
                                      const float4 w0, const float4 w1,
                                      const float2 v0, const float2 v1,
                                      const float2 v2, const float2 v3)
{
    re  = w0.x * v0.x - w0.y * v0.y;
    im  = w0.y * v0.x + w0.x * v0.y;
    re += w0.z * v1.x - w0.w * v1.y;
    im += w0.w * v1.x + w0.z * v1.y;
    re += w1.x * v2.x - w1.y * v2.y;
    im += w1.y * v2.x + w1.x * v2.y;
    re += w1.z * v3.x - w1.w * v3.y;
    im += w1.w * v3.x + w1.z * v3.y;
}

__global__ void __launch_bounds__(256, 1)
beamform_kernel(const float* __restrict__ in0,
                const float* __restrict__ in1,
                const float* __restrict__ in2,
                const float* __restrict__ in3,
                const float* __restrict__ bf,
                float* __restrict__ out,
                int quarter_blocks,    // Bc / 4
                int blocks_per_ch)     // Bc
{
    const int g = blockIdx.x * blockDim.x + threadIdx.x;
    if (g >= quarter_blocks * 5) return;

    const int ch = blockIdx.y;
    const float* __restrict__ in =
        (ch == 0) ? in0 : (ch == 1) ? in1 : (ch == 2) ? in2 : in3;

    const int b = g / 5;            // block within first quarter
    const int j = g - b * 5;        // column 0..4

    const size_t qstride = (size_t)quarter_blocks * 20;   // float2 per quarter

    // ---- front-batched loads: 16 independent LDG.64, 4 compact windows ----
    const float2* __restrict__ pA =
        (const float2*)(in + (size_t)b * 40 + 2 * j);
    const float2* __restrict__ pB = pA + qstride;
    const float2* __restrict__ pC = pB + qstride;
    const float2* __restrict__ pD = pC + qstride;

    const float2 a0 = __ldg(pA + 0),  a1 = __ldg(pA + 5);
    const float2 a2 = __ldg(pA + 10), a3 = __ldg(pA + 15);
    const float2 b0 = __ldg(pB + 0),  b1 = __ldg(pB + 5);
    const float2 b2 = __ldg(pB + 10), b3 = __ldg(pB + 15);
    const float2 c0 = __ldg(pC + 0),  c1 = __ldg(pC + 5);
    const float2 c2 = __ldg(pC + 10), c3 = __ldg(pC + 15);
    const float2 d0 = __ldg(pD + 0),  d1 = __ldg(pD + 5);
    const float2 d2 = __ldg(pD + 10), d3 = __ldg(pD + 15);

    // weights: uniform-address broadcast, L1-resident
    const float4 w0 = __ldg((const float4*)bf);      // br0, bi0, br1, bi1
    const float4 w1 = __ldg((const float4*)bf + 1);  // br2, bi2, br3, bi3

    float reA, imA, reB, imB, reC, imC, reD, imD;
    cmac4(reA, imA, w0, w1, a0, a1, a2, a3);
    cmac4(reB, imB, w0, w1, b0, b1, b2, b3);
    cmac4(reC, imC, w0, w1, c0, c1, c2, c3);
    cmac4(reD, imD, w0, w1, d0, d1, d2, d3);

    const size_t oq = (size_t)quarter_blocks * 10;
    const size_t ob = ((size_t)ch * blocks_per_ch + (size_t)b) * 10;
    out[ob + j]              = reA;
    out[ob + 5 + j]          = imA;
    out[ob + oq + j]         = reB;
    out[ob + oq + 5 + j]     = imB;
    out[ob + 2 * oq + j]     = reC;
    out[ob + 2 * oq + 5 + j] = imC;
    out[ob + 3 * oq + j]     = reD;
    out[ob + 3 * oq + 5 + j] = imD;
}

extern "C" void kernel_launch(void* const* d_in, const int* in_sizes, int n_in,
                              void* d_out, int out_size)
{
    const float* in0 = (const float*)d_in[0];
    const float* in1 = (const float*)d_in[1];
    const float* in2 = (const float*)d_in[2];
    const float* in3 = (const float*)d_in[3];
    const float* bf  = (const float*)d_in[4];
    float* out = (float*)d_out;

    const int N  = in_sizes[0];          // 20,000,000 floats / channel
    const int Bc = N / 40;               // 500,000 beam blocks per channel
    const int Qb = Bc / 4;               // 125,000 blocks per quarter

    const int threads = 256;
    const int n_thr = Qb * 5;            // 625,000 threads per channel
    dim3 grid((n_thr + threads - 1) / threads, 4);

    beamform_kernel<<<grid, threads>>>(in0, in1, in2, in3, bf, out, Qb, Bc);
}

// round 8
// speedup vs baseline: 1.0661x; 1.0310x over previous
#include <cuda_runtime.h>

// Beamform_1649267442279 — GB300 sm_103a — R8: R5 (best: 59.2us kernel,
// DRAM 81.7%) + streaming stores (__stcs). Output is write-once/never-read:
// evict-first stores keep L2 ways free for the input lines, which each need
// to survive 4 LDG touches (the reuse that __ldcs on LOADS destroyed in R3).
//
// Semantics: per channel s, blocks of 20 complex samples (40 floats).
// Block b, row r (0..3), col c (0..4):
//   re[r,c] = in_s[40b + 10r + 2c],  im[r,c] = in_s[40b + 10r + 2c + 1]
//   out[(s*Bc+b)*10 + c]     = sum_r br[r]*re - bi[r]*im
//   out[(s*Bc+b)*10 + 5 + c] = sum_r bi[r]*re + br[r]*im
// with br[r]=bf[2r], bi[r]=bf[2r+1].
//
// Mapping (R5): thread (g, ch), g = b*5 + j, handles col j of blocks b and
// b + Bc/2. 8 independent front-batched LDG.64, two compact 1KB warp windows.

__global__ void __launch_bounds__(256)
beamform_kernel(const float* __restrict__ in0,
                const float* __restrict__ in1,
                const float* __restrict__ in2,
                const float* __restrict__ in3,
                const float* __restrict__ bf,
                float* __restrict__ out,
                int half_blocks,       // Bc / 2
                int blocks_per_ch)     // Bc
{
    const int g = blockIdx.x * blockDim.x + threadIdx.x;
    if (g >= half_blocks * 5) return;

    const int ch = blockIdx.y;
    const float* __restrict__ in =
        (ch == 0) ? in0 : (ch == 1) ? in1 : (ch == 2) ? in2 : in3;

    const int b = g / 5;            // block in first half
    const int j = g - b * 5;        // column 0..4

    // ---- front-batched loads: 8 independent LDG.64, two compact windows ----
    const float2* __restrict__ pA =
        (const float2*)(in + (size_t)b * 40 + 2 * j);
    const float2* __restrict__ pB = pA + (size_t)half_blocks * 20;  // +Bc/2 blocks

    const float2 a0 = __ldg(pA + 0);
    const float2 a1 = __ldg(pA + 5);
    const float2 a2 = __ldg(pA + 10);
    const float2 a3 = __ldg(pA + 15);
    const float2 c0 = __ldg(pB + 0);
    const float2 c1 = __ldg(pB + 5);
    const float2 c2 = __ldg(pB + 10);
    const float2 c3 = __ldg(pB + 15);

    // weights: uniform-address broadcast, L1-resident
    const float4 w0 = __ldg((const float4*)bf);      // br0, bi0, br1, bi1
    const float4 w1 = __ldg((const float4*)bf + 1);  // br2, bi2, br3, bi3

    float reA = w0.x * a0.x - w0.y * a0.y;
    float imA = w0.y * a0.x + w0.x * a0.y;
    reA += w0.z * a1.x - w0.w * a1.y;
    imA += w0.w * a1.x + w0.z * a1.y;
    reA += w1.x * a2.x - w1.y * a2.y;
    imA += w1.y * a2.x + w1.x * a2.y;
    reA += w1.z * a3.x - w1.w * a3.y;
    imA += w1.w * a3.x + w1.z * a3.y;

    float reB = w0.x * c0.x - w0.y * c0.y;
    float imB = w0.y * c0.x + w0.x * c0.y;
    reB += w0.z * c1.x - w0.w * c1.y;
    imB += w0.w * c1.x + w0.z * c1.y;
    reB += w1.x * c2.x - w1.y * c2.y;
    imB += w1.y * c2.x + w1.x * c2.y;
    reB += w1.z * c3.x - w1.w * c3.y;
    imB += w1.w * c3.x + w1.z * c3.y;

    const size_t obA = ((size_t)ch * blocks_per_ch + (size_t)b) * 10;
    const size_t obB = obA + (size_t)half_blocks * 10;

    // streaming stores: output is never re-read, don't pollute L2
    __stcs(out + obA + j,     reA);
    __stcs(out + obA + 5 + j, imA);
    __stcs(out + obB + j,     reB);
    __stcs(out + obB + 5 + j, imB);
}

extern "C" void kernel_launch(void* const* d_in, const int* in_sizes, int n_in,
                              void* d_out, int out_size)
{
    const float* in0 = (const float*)d_in[0];
    const float* in1 = (const float*)d_in[1];
    const float* in2 = (const float*)d_in[2];
    const float* in3 = (const float*)d_in[3];
    const float* bf  = (const float*)d_in[4];
    float* out = (float*)d_out;

    const int N  = in_sizes[0];          // 20,000,000 floats / channel
    const int Bc = N / 40;               // 500,000 beam blocks per channel
    const int Hb = Bc / 2;               // 250,000 blocks in each half

    const int threads = 256;
    const int n_thr = Hb * 5;            // 1.25M threads per channel
    dim3 grid((n_thr + threads - 1) / threads, 4);

    beamform_kernel<<<grid, threads>>>(in0, in1, in2, in3, bf, out, Hb, Bc);
}